// round 12
// baseline (speedup 1.0000x reference)
#include <cuda_runtime.h>
#include <cuda_bf16.h>
#include <cstdint>
#include <math_constants.h>

#define NROWS 8192
#define KDIM  768
#define GRID_TILES ((NROWS / 128) * (NROWS / 128))   // 4096 CTAs in gemm grid

// ---------------- scratch (__device__ globals; no allocations) -------------
__device__ __nv_bfloat16 g_xn[NROWS * KDIM];
__device__ __nv_bfloat16 g_yn[NROWS * KDIM];
__device__ float g_rowmax[NROWS];
__device__ int   g_ticket;

// ---------------------------------------------------------------------------
// Fused: one warp per row; blocks [0, NROWS/8) handle ex, rest handle ey.
// Also inits g_rowmax (ex half) and resets the gemm ticket.
__global__ void normalize_kernel(const float* __restrict__ ex,
                                 const float* __restrict__ ey) {
    const int half = NROWS / 8;                      // blocks per tensor
    const int which = (blockIdx.x >= half) ? 1 : 0;
    const int blk = which ? (blockIdx.x - half) : blockIdx.x;
    const float* src = which ? ey : ex;
    __nv_bfloat16* dst = which ? g_yn : g_xn;

    if (blockIdx.x == 0 && threadIdx.x == 0) g_ticket = 0;

    int warp = blk * 8 + (threadIdx.x >> 5);
    int lane = threadIdx.x & 31;
    if (warp >= NROWS) return;

    if (which == 0 && lane == 0) g_rowmax[warp] = -CUDART_INF_F;

    const float4* p = reinterpret_cast<const float4*>(src + (size_t)warp * KDIM);
    float4 v[6];
    float s = 0.f;
#pragma unroll
    for (int i = 0; i < 6; i++) {
        v[i] = p[i * 32 + lane];
        s += v[i].x * v[i].x + v[i].y * v[i].y + v[i].z * v[i].z + v[i].w * v[i].w;
    }
#pragma unroll
    for (int o = 16; o > 0; o >>= 1) s += __shfl_xor_sync(0xffffffffu, s, o);
    float inv = (s > 0.f) ? (1.0f / sqrtf(s)) : 0.f;

    __nv_bfloat162* d2 = reinterpret_cast<__nv_bfloat162*>(dst + (size_t)warp * KDIM);
#pragma unroll
    for (int i = 0; i < 6; i++) {
        float2 lo = make_float2(v[i].x * inv, v[i].y * inv);
        float2 hi = make_float2(v[i].z * inv, v[i].w * inv);
        d2[(i * 32 + lane) * 2]     = __float22bfloat162_rn(lo);
        d2[(i * 32 + lane) * 2 + 1] = __float22bfloat162_rn(hi);
    }
}

__device__ __forceinline__ void atomicMaxF(float* addr, float v) {
    if (v >= 0.f) atomicMax((int*)addr, __float_as_int(v));
    else          atomicMin((unsigned int*)addr, __float_as_uint(v));
}

// ---------------- smem: 3 stages, K-chunk 64 (128B rows, SW128) ------------
#define STAGES 3
#define A_STAGE_BYTES (128 * 128)
#define B_STAGE_BYTES (128 * 128)
#define SA_OFF(s) ((s) * A_STAGE_BYTES)
#define SB_OFF(s) (STAGES * A_STAGE_BYTES + (s) * B_STAGE_BYTES)
#define SMEM_TOTAL (STAGES * (A_STAGE_BYTES + B_STAGE_BYTES))   // 96 KB

// issue cp.async for one stage: A 128 rows, B 128 rows, 64 bf16 cols. 256 thr.
__device__ __forceinline__ void load_stage(uint32_t aBase, uint32_t bBase,
                                           int mbase, int nbase, int k0, int tid) {
#pragma unroll
    for (int j = 0; j < 4; j++) {            // A: 1024 16B chunks / 256 thr
        int idx = j * 256 + tid;
        int row = idx >> 3, ck = idx & 7;
        int off = row * 128 + ck * 16;
        off ^= (off >> 3) & 0x70;
        const void* src = &g_xn[(size_t)(mbase + row) * KDIM + k0 + ck * 8];
        asm volatile("cp.async.cg.shared.global [%0], [%1], 16;"
                     :: "r"(aBase + off), "l"(src));
    }
#pragma unroll
    for (int j = 0; j < 4; j++) {            // B: 1024 16B chunks / 256 thr
        int idx = j * 256 + tid;
        int row = idx >> 3, ck = idx & 7;
        int off = row * 128 + ck * 16;
        off ^= (off >> 3) & 0x70;
        const void* src = &g_yn[(size_t)(nbase + row) * KDIM + k0 + ck * 8];
        asm volatile("cp.async.cg.shared.global [%0], [%1], 16;"
                     :: "r"(bBase + off), "l"(src));
    }
}

// ---------------------------------------------------------------------------
// GEMM + fused row-max + last-CTA finalize. Block 128x128, 8 warps 4(M)x2(N),
// warp tile 32x64, mma.sync.m16n8k16.bf16, 3-stage cp.async, occupancy 2.
// ---------------------------------------------------------------------------
__global__ void __launch_bounds__(256, 2) gemm_rowmax_kernel(float* out) {
    extern __shared__ char smem[];
    const uint32_t sbase = (uint32_t)__cvta_generic_to_shared(smem);

    const int tid  = threadIdx.x;
    const int lane = tid & 31;
    const int warp = tid >> 5;
    const int wm = warp & 3;        // 0..3 : 32 M-rows each
    const int wn = warp >> 2;       // 0..1 : 64 N-cols each
    const int mbase = blockIdx.x * 128;
    const int nbase = blockIdx.y * 128;

    float acc[2][8][4];
#pragma unroll
    for (int i = 0; i < 2; i++)
#pragma unroll
        for (int j = 0; j < 8; j++)
#pragma unroll
            for (int c = 0; c < 4; c++) acc[i][j][c] = 0.f;

    const int NIT = KDIM / 64;      // 12

    // prologue: stages 0,1 <- chunks 0,1
#pragma unroll
    for (int s = 0; s < 2; s++) {
        load_stage(sbase + SA_OFF(s), sbase + SB_OFF(s), mbase, nbase, s * 64, tid);
        asm volatile("cp.async.commit_group;" ::: "memory");
    }

    // per-thread swizzled ldmatrix offsets (stage-relative)
    int aoff[2], boff[4];
#pragma unroll
    for (int mi = 0; mi < 2; mi++) {
        int r  = wm * 32 + mi * 16 + (lane & 15);
        int kc = (lane >> 4) << 3;
        int off = r * 128 + kc * 2;
        aoff[mi] = off ^ ((off >> 3) & 0x70);
    }
#pragma unroll
    for (int np = 0; np < 4; np++) {
        int n  = wn * 64 + np * 16 + (lane & 7) + ((lane >> 4) << 3);
        int kc = ((lane >> 3) & 1) << 3;
        int off = n * 128 + kc * 2;
        boff[np] = off ^ ((off >> 3) & 0x70);
    }

    for (int i = 0; i < NIT; i++) {
        if (i + 1 < NIT) { asm volatile("cp.async.wait_group 1;" ::: "memory"); }
        else             { asm volatile("cp.async.wait_group 0;" ::: "memory"); }
        __syncthreads();   // chunk i ready everywhere; stage (i+2)%3 free

        if (i + 2 < NIT) {
            int s = (i + 2) % 3;
            load_stage(sbase + SA_OFF(s), sbase + SB_OFF(s),
                       mbase, nbase, (i + 2) * 64, tid);
            asm volatile("cp.async.commit_group;" ::: "memory");
        }

        const uint32_t aS = sbase + SA_OFF(i % 3);
        const uint32_t bS = sbase + SB_OFF(i % 3);

#pragma unroll
        for (int ks = 0; ks < 4; ks++) {
            const int kb = ks * 32;   // 16 cols = 32B; XOR-safe under SW128

            uint32_t a[2][4];
#pragma unroll
            for (int mi = 0; mi < 2; mi++) {
                uint32_t addr = aS + (uint32_t)(aoff[mi] ^ kb);
                asm volatile("ldmatrix.sync.aligned.m8n8.x4.shared.b16 {%0,%1,%2,%3}, [%4];"
                             : "=r"(a[mi][0]), "=r"(a[mi][1]),
                               "=r"(a[mi][2]), "=r"(a[mi][3]) : "r"(addr));
            }
            uint32_t b[8][2];
#pragma unroll
            for (int np = 0; np < 4; np++) {
                uint32_t addr = bS + (uint32_t)(boff[np] ^ kb);
                asm volatile("ldmatrix.sync.aligned.m8n8.x4.shared.b16 {%0,%1,%2,%3}, [%4];"
                             : "=r"(b[2 * np][0]), "=r"(b[2 * np][1]),
                               "=r"(b[2 * np + 1][0]), "=r"(b[2 * np + 1][1])
                             : "r"(addr));
            }
#pragma unroll
            for (int mi = 0; mi < 2; mi++)
#pragma unroll
                for (int nt = 0; nt < 8; nt++) {
                    asm volatile(
                        "mma.sync.aligned.m16n8k16.row.col.f32.bf16.bf16.f32 "
                        "{%0,%1,%2,%3}, {%4,%5,%6,%7}, {%8,%9}, {%0,%1,%2,%3};"
                        : "+f"(acc[mi][nt][0]), "+f"(acc[mi][nt][1]),
                          "+f"(acc[mi][nt][2]), "+f"(acc[mi][nt][3])
                        : "r"(a[mi][0]), "r"(a[mi][1]), "r"(a[mi][2]), "r"(a[mi][3]),
                          "r"(b[nt][0]), "r"(b[nt][1]));
                }
        }
    }

    // ---- epilogue: per-row max over this block's 128 columns ----
#pragma unroll
    for (int mi = 0; mi < 2; mi++) {
        float r0 = -CUDART_INF_F, r1 = -CUDART_INF_F;
#pragma unroll
        for (int nt = 0; nt < 8; nt++) {
            r0 = fmaxf(r0, fmaxf(acc[mi][nt][0], acc[mi][nt][1]));
            r1 = fmaxf(r1, fmaxf(acc[mi][nt][2], acc[mi][nt][3]));
        }
#pragma unroll
        for (int o = 1; o <= 2; o <<= 1) {
            r0 = fmaxf(r0, __shfl_xor_sync(0xffffffffu, r0, o));
            r1 = fmaxf(r1, __shfl_xor_sync(0xffffffffu, r1, o));
        }
        if ((lane & 3) == 0) {
            int row = mbase + wm * 32 + mi * 16 + (lane >> 2);
            atomicMaxF(&g_rowmax[row], r0);
            atomicMaxF(&g_rowmax[row + 8], r1);
        }
    }

    // ---- last-CTA finalize: lp = Normal(1,0.3).log_prob; sum exp(lp)*lp ----
    __shared__ int s_last;
    __syncthreads();                  // all row-max atomics of this CTA issued
    if (tid == 0) {
        __threadfence();              // make atomics visible before ticket
        s_last = (atomicAdd(&g_ticket, 1) == GRID_TILES - 1);
    }
    __syncthreads();
    if (s_last) {
        __shared__ double red[8];
        __threadfence();
        double s = 0.0;
        for (int i = tid; i < NROWS; i += 256) {
            float mv = __ldcg(&g_rowmax[i]);      // L2-coherent read
            float z = (mv - 1.0f) * (1.0f / 0.3f);
            float lp = fmaf(-0.5f * z, z, 0.2850342711212634f);
            s += (double)(expf(lp) * lp);
        }
#pragma unroll
        for (int o = 16; o > 0; o >>= 1) s += __shfl_xor_sync(0xffffffffu, s, o);
        if (lane == 0) red[warp] = s;
        __syncthreads();
        if (warp == 0) {
            double t = (lane < 8) ? red[lane] : 0.0;
#pragma unroll
            for (int o = 4; o > 0; o >>= 1) t += __shfl_xor_sync(0xffffffffu, t, o);
            if (lane == 0) out[0] = (float)t;
        }
    }
}

// ---------------------------------------------------------------------------
extern "C" void kernel_launch(void* const* d_in, const int* in_sizes, int n_in,
                              void* d_out, int out_size) {
    const float* ex = (const float*)d_in[0];
    const float* ey = (const float*)d_in[1];
    float* out = (float*)d_out;

    cudaFuncSetAttribute(gemm_rowmax_kernel,
                         cudaFuncAttributeMaxDynamicSharedMemorySize, SMEM_TOTAL);

    normalize_kernel<<<NROWS / 4, 256>>>(ex, ey);   // both tensors, one launch

    dim3 grid(NROWS / 128, NROWS / 128);   // 64 x 64 = 4096 CTAs
    gemm_rowmax_kernel<<<grid, 256, SMEM_TOTAL>>>(out);
}